// round 1
// baseline (speedup 1.0000x reference)
#include <cuda_runtime.h>
#include <math_constants.h>

// DynamicRouter: logits = x @ W^T + b + 0.1*noise ; top-2 ; sparse softmax.
// x:[32768,768] f32, W:[8,768], b:[8], noise:[32768,8]
// out: [32768*8] probs followed by [32768*2] top-k indices (as f32).
//
// Mapping: 1 warp = 8 tokens (one per quad of 4 lanes).
//   - lane r (=lane&3) of a quad loads float4s of its token row at dim r*4 + 16*j
//     -> 64B contiguous per token per step, fully-used sectors, no smem staging.
//   - W in smem; lanes with equal r read identical addresses (8-way broadcast,
//     4 distinct 16B words per LDS.128 -> conflict-free single wavefront).
//   - quad reduce: 2 SHFL.BFLY rounds x 8 accumulators.

#define ROUTER_D 768
#define ROUTER_E 8

__global__ __launch_bounds__(256, 4)
void dynamic_router_kernel(const float* __restrict__ x,
                           const float* __restrict__ W,
                           const float* __restrict__ b,
                           const float* __restrict__ noise,
                           float* __restrict__ out,
                           int n_tokens, long long out_size)
{
    __shared__ float Ws[ROUTER_E * ROUTER_D];
    __shared__ float bs[ROUTER_E];

    const int tid = threadIdx.x;

    // One-time: stage W (24KB) + b into smem, coalesced float4 copies.
    {
        const float4* W4 = reinterpret_cast<const float4*>(W);
        float4* Ws4 = reinterpret_cast<float4*>(Ws);
        #pragma unroll
        for (int i = tid; i < ROUTER_E * ROUTER_D / 4; i += 256)
            Ws4[i] = W4[i];
        if (tid < ROUTER_E) bs[tid] = b[tid];
    }
    __syncthreads();

    const int warp = tid >> 5;
    const int lane = tid & 31;
    const int r    = lane & 3;   // position within quad
    const int quad = lane >> 2;  // 0..7

    // block handles 64 tokens: 8 warps x 8 tokens
    const int token = (blockIdx.x * 8 + warp) * 8 + quad;
    const bool valid = token < n_tokens;

    float acc[ROUTER_E];
    #pragma unroll
    for (int e = 0; e < ROUTER_E; ++e) acc[e] = 0.0f;

    if (valid) {
        const float4* xr = reinterpret_cast<const float4*>(x + (size_t)token * ROUTER_D);
        #pragma unroll
        for (int j = 0; j < ROUTER_D / 16; ++j) {        // 48 steps of 16 dims, 4 per lane
            const float4 xv = xr[j * 4 + r];
            const float4* wb = reinterpret_cast<const float4*>(Ws) + (j * 4 + r);
            #pragma unroll
            for (int e = 0; e < ROUTER_E; ++e) {
                const float4 wv = wb[e * (ROUTER_D / 4)];
                acc[e] = fmaf(xv.x, wv.x,
                         fmaf(xv.y, wv.y,
                         fmaf(xv.z, wv.z,
                         fmaf(xv.w, wv.w, acc[e]))));
            }
        }
    }

    // quad reduction (all lanes participate; garbage lanes harmless)
    #pragma unroll
    for (int e = 0; e < ROUTER_E; ++e) {
        acc[e] += __shfl_xor_sync(0xffffffffu, acc[e], 1);
        acc[e] += __shfl_xor_sync(0xffffffffu, acc[e], 2);
    }

    if (valid && r == 0) {
        const float4 n0 = *reinterpret_cast<const float4*>(noise + (size_t)token * ROUTER_E);
        const float4 n1 = *reinterpret_cast<const float4*>(noise + (size_t)token * ROUTER_E + 4);

        float lg[ROUTER_E];
        lg[0] = acc[0] + bs[0] + 0.1f * n0.x;
        lg[1] = acc[1] + bs[1] + 0.1f * n0.y;
        lg[2] = acc[2] + bs[2] + 0.1f * n0.z;
        lg[3] = acc[3] + bs[3] + 0.1f * n0.w;
        lg[4] = acc[4] + bs[4] + 0.1f * n1.x;
        lg[5] = acc[5] + bs[5] + 0.1f * n1.y;
        lg[6] = acc[6] + bs[6] + 0.1f * n1.z;
        lg[7] = acc[7] + bs[7] + 0.1f * n1.w;

        // top-1 (strict > keeps lowest index on ties, matching jax.lax.top_k)
        int m1 = 0; float v1 = lg[0];
        #pragma unroll
        for (int e = 1; e < ROUTER_E; ++e)
            if (lg[e] > v1) { v1 = lg[e]; m1 = e; }
        // top-2
        int m2 = -1; float v2 = -CUDART_INF_F;
        #pragma unroll
        for (int e = 0; e < ROUTER_E; ++e)
            if (e != m1 && lg[e] > v2) { v2 = lg[e]; m2 = e; }

        // softmax over {v1, v2}, zeros elsewhere (exp(-inf)=0)
        const float ex  = __expf(v2 - v1);      // <= 1
        const float inv = 1.0f / (1.0f + ex);
        const float p1  = inv;
        const float p2  = ex * inv;

        float pv[ROUTER_E];
        #pragma unroll
        for (int e = 0; e < ROUTER_E; ++e)
            pv[e] = (e == m1) ? p1 : ((e == m2) ? p2 : 0.0f);

        float4* o = reinterpret_cast<float4*>(out + (size_t)token * ROUTER_E);
        o[0] = make_float4(pv[0], pv[1], pv[2], pv[3]);
        o[1] = make_float4(pv[4], pv[5], pv[6], pv[7]);

        // second output: top-k indices (stored as float32 after all probs)
        const long long probs = (long long)n_tokens * ROUTER_E;
        if (out_size >= probs + (long long)n_tokens * 2) {
            float2 iv = make_float2((float)m1, (float)m2);
            *reinterpret_cast<float2*>(out + probs + (size_t)token * 2) = iv;
        }
    }
}

extern "C" void kernel_launch(void* const* d_in, const int* in_sizes, int n_in,
                              void* d_out, int out_size)
{
    const float* x     = (const float*)d_in[0];
    const float* W     = (const float*)d_in[1];
    const float* b     = (const float*)d_in[2];
    const float* noise = (const float*)d_in[3];
    float* out = (float*)d_out;

    const int n_tokens = in_sizes[0] / ROUTER_D;      // 32768
    const int blocks   = (n_tokens + 63) / 64;        // 64 tokens per block

    dynamic_router_kernel<<<blocks, 256>>>(x, W, b, noise, out,
                                           n_tokens, (long long)out_size);
}

// round 4
// speedup vs baseline: 1.0960x; 1.0960x over previous
#include <cuda_runtime.h>
#include <math_constants.h>

// DynamicRouter: logits = x @ W^T + b + 0.1*noise ; top-2 ; sparse softmax.
// x:[32768,768] f32, W:[8,768], b:[8], noise:[32768,8]
// out: [32768*8] probs, then [32768*2] top-k indices (as f32).
//
// R1 lesson: LDS broadcast of W costs 4 phases/instr at 50% utilization ->
// L1-wavefront bound (216 wf/token). This version reads W via LDG (.nc):
// W (24KB) is L1-resident; each W LDG.128 touches one 64B-aligned block
// (4 distinct 16B words, 8-way warp broadcast) -> 1 wavefront/instr.
// 72 wf/token total -> HBM becomes the binding constraint (~14us).
// FMA issue halved with packed fma.rn.f32x2.

#define ROUTER_D 768
#define ROUTER_E 8

__device__ __forceinline__ unsigned long long pack2(float lo, float hi) {
    unsigned long long r;
    asm("mov.b64 %0, {%1, %2};" : "=l"(r) : "f"(lo), "f"(hi));
    return r;
}
__device__ __forceinline__ void fma_x2(unsigned long long& d,
                                       unsigned long long a,
                                       unsigned long long b) {
    asm("fma.rn.f32x2 %0, %1, %2, %3;" : "=l"(d) : "l"(a), "l"(b), "l"(d));
}
__device__ __forceinline__ float2 unpack2(unsigned long long v) {
    float lo, hi;
    asm("mov.b64 {%0, %1}, %2;" : "=f"(lo), "=f"(hi) : "l"(v));
    return make_float2(lo, hi);
}

__global__ __launch_bounds__(256)
void dynamic_router_kernel(const float* __restrict__ x,
                           const float* __restrict__ W,
                           const float* __restrict__ b,
                           const float* __restrict__ noise,
                           float* __restrict__ out,
                           int n_tokens, long long out_size)
{
    const int tid  = threadIdx.x;
    const int warp = tid >> 5;
    const int lane = tid & 31;
    const int r    = lane & 3;   // position within quad (covers 16 dims/step: 4 each)
    const int quad = lane >> 2;  // 0..7 -> token within warp

    const int token = (blockIdx.x * 8 + warp) * 8 + quad;
    const bool valid = token < n_tokens;

    unsigned long long acc[ROUTER_E];
    #pragma unroll
    for (int e = 0; e < ROUTER_E; ++e) acc[e] = 0ull;

    if (valid) {
        const float4* xr = reinterpret_cast<const float4*>(x + (size_t)token * ROUTER_D);
        const float4* wp = reinterpret_cast<const float4*>(W) + r;

        #pragma unroll 8
        for (int j = 0; j < ROUTER_D / 16; ++j) {      // 48 steps of 16 dims
            const float4 xv = __ldg(&xr[j * 4 + r]);
            const unsigned long long x01 = pack2(xv.x, xv.y);
            const unsigned long long x23 = pack2(xv.z, xv.w);
            #pragma unroll
            for (int e = 0; e < ROUTER_E; ++e) {
                // addr = W + e*768 + j*16 + r*4 floats: 4 r-words in one 64B block
                const float4 wv = __ldg(&wp[e * (ROUTER_D / 4) + j * 4]);
                fma_x2(acc[e], x01, pack2(wv.x, wv.y));
                fma_x2(acc[e], x23, pack2(wv.z, wv.w));
            }
        }
    }

    // horizontal within the packed pair, then quad reduction
    float av[ROUTER_E];
    #pragma unroll
    for (int e = 0; e < ROUTER_E; ++e) {
        const float2 p = unpack2(acc[e]);
        av[e] = p.x + p.y;
        av[e] += __shfl_xor_sync(0xffffffffu, av[e], 1);
        av[e] += __shfl_xor_sync(0xffffffffu, av[e], 2);
    }

    if (valid && r == 0) {
        const float4 n0 = __ldg(reinterpret_cast<const float4*>(noise + (size_t)token * ROUTER_E));
        const float4 n1 = __ldg(reinterpret_cast<const float4*>(noise + (size_t)token * ROUTER_E) + 1);

        float lg[ROUTER_E];
        lg[0] = av[0] + __ldg(b + 0) + 0.1f * n0.x;
        lg[1] = av[1] + __ldg(b + 1) + 0.1f * n0.y;
        lg[2] = av[2] + __ldg(b + 2) + 0.1f * n0.z;
        lg[3] = av[3] + __ldg(b + 3) + 0.1f * n0.w;
        lg[4] = av[4] + __ldg(b + 4) + 0.1f * n1.x;
        lg[5] = av[5] + __ldg(b + 5) + 0.1f * n1.y;
        lg[6] = av[6] + __ldg(b + 6) + 0.1f * n1.z;
        lg[7] = av[7] + __ldg(b + 7) + 0.1f * n1.w;

        // top-1 (strict > keeps lowest index on ties, matching jax.lax.top_k)
        int m1 = 0; float v1 = lg[0];
        #pragma unroll
        for (int e = 1; e < ROUTER_E; ++e)
            if (lg[e] > v1) { v1 = lg[e]; m1 = e; }
        // top-2
        int m2 = -1; float v2 = -CUDART_INF_F;
        #pragma unroll
        for (int e = 0; e < ROUTER_E; ++e)
            if (e != m1 && lg[e] > v2) { v2 = lg[e]; m2 = e; }

        // softmax over {v1, v2}, zeros elsewhere (exp(-inf)=0)
        const float ex  = __expf(v2 - v1);      // <= 1
        const float inv = 1.0f / (1.0f + ex);
        const float p1  = inv;
        const float p2  = ex * inv;

        float pv[ROUTER_E];
        #pragma unroll
        for (int e = 0; e < ROUTER_E; ++e)
            pv[e] = (e == m1) ? p1 : ((e == m2) ? p2 : 0.0f);

        float4* o = reinterpret_cast<float4*>(out + (size_t)token * ROUTER_E);
        o[0] = make_float4(pv[0], pv[1], pv[2], pv[3]);
        o[1] = make_float4(pv[4], pv[5], pv[6], pv[7]);

        // second output: top-k indices (stored as float32 after all probs)
        const long long probs = (long long)n_tokens * ROUTER_E;
        if (out_size >= probs + (long long)n_tokens * 2) {
            float2 iv = make_float2((float)m1, (float)m2);
            *reinterpret_cast<float2*>(out + probs + (size_t)token * 2) = iv;
        }
    }
}

extern "C" void kernel_launch(void* const* d_in, const int* in_sizes, int n_in,
                              void* d_out, int out_size)
{
    const float* x     = (const float*)d_in[0];
    const float* W     = (const float*)d_in[1];
    const float* b     = (const float*)d_in[2];
    const float* noise = (const float*)d_in[3];
    float* out = (float*)d_out;

    const int n_tokens = in_sizes[0] / ROUTER_D;      // 32768
    const int blocks   = (n_tokens + 63) / 64;        // 64 tokens per block

    dynamic_router_kernel<<<blocks, 256>>>(x, W, b, noise, out,
                                           n_tokens, (long long)out_size);
}

// round 7
// speedup vs baseline: 1.5895x; 1.4503x over previous
#include <cuda_runtime.h>
#include <math_constants.h>

// DynamicRouter: logits = x @ W^T + b + 0.1*noise ; top-2 ; sparse softmax.
// x:[32768,768] f32, W:[8,768], b:[8], noise:[32768,8]
// out: [32768*8] probs, then [32768*2] top-k indices (as f32).
//
// Octet mapping: 8 lanes x 16B = one full 128B line of ONE token per LDG
// phase -> x at the 24 wf/token minimum. Register tile T=4 tokens per octet
// group amortizes each W load 4x -> 72 wf/token total; HBM (~14us) binds.
// R6 fix: ulonglong2 indices are 16B (4-float) units: x elem = j*8 + o,
// W elem = e*192 + j*8 + o (previous round indexed in 8B units -> wrong dims).

#define ROUTER_D 768
#define ROUTER_E 8
#define TOK_T    4

__device__ __forceinline__ void fma_x2(unsigned long long& d,
                                       unsigned long long a,
                                       unsigned long long b) {
    asm("fma.rn.f32x2 %0, %1, %2, %3;" : "=l"(d) : "l"(a), "l"(b), "l"(d));
}
__device__ __forceinline__ float2 unpack2(unsigned long long v) {
    float lo, hi;
    asm("mov.b64 {%0, %1}, %2;" : "=f"(lo), "=f"(hi) : "l"(v));
    return make_float2(lo, hi);
}

__global__ __launch_bounds__(128)
void dynamic_router_kernel(const float* __restrict__ x,
                           const float* __restrict__ W,
                           const float* __restrict__ b,
                           const float* __restrict__ noise,
                           float* __restrict__ out,
                           int n_tokens, long long out_size)
{
    const int tid  = threadIdx.x;
    const int warp = tid >> 5;
    const int lane = tid & 31;
    const int o    = lane & 7;   // 16B slot within a 128B (32-dim) step
    const int g    = lane >> 3;  // octet group 0..3

    // warp covers 16 tokens: token(t) = base + t*4 + g
    const int base = (blockIdx.x * 4 + warp) * (4 * TOK_T);

    // Row bases in 16B units (ulonglong2 = 4 floats)
    const ulonglong2* xr[TOK_T];
    #pragma unroll
    for (int t = 0; t < TOK_T; ++t) {
        int tk = base + t * 4 + g;
        tk = tk < n_tokens ? tk : 0;                   // clamp; stores guarded
        xr[t] = reinterpret_cast<const ulonglong2*>(x + (size_t)tk * ROUTER_D);
    }
    const ulonglong2* wr = reinterpret_cast<const ulonglong2*>(W);

    unsigned long long acc[TOK_T][ROUTER_E];
    #pragma unroll
    for (int t = 0; t < TOK_T; ++t)
        #pragma unroll
        for (int e = 0; e < ROUTER_E; ++e) acc[t][e] = 0ull;

    #pragma unroll 2
    for (int j = 0; j < ROUTER_D / 32; ++j) {          // 24 steps of 32 dims
        const int idx = j * 8 + o;                     // 16B-unit index in row
        ulonglong2 wv[ROUTER_E];
        #pragma unroll
        for (int e = 0; e < ROUTER_E; ++e)
            wv[e] = __ldg(&wr[e * (ROUTER_D / 4) + idx]);   // e*192 + j*8 + o
        ulonglong2 xv[TOK_T];
        #pragma unroll
        for (int t = 0; t < TOK_T; ++t)
            xv[t] = __ldg(&xr[t][idx]);

        #pragma unroll
        for (int t = 0; t < TOK_T; ++t)
            #pragma unroll
            for (int e = 0; e < ROUTER_E; ++e) {
                fma_x2(acc[t][e], xv[t].x, wv[e].x);
                fma_x2(acc[t][e], xv[t].y, wv[e].y);
            }
    }

    // Reduce across the 8 lanes of the octet for each (t, e).
    // Lane with o == t keeps token t's logits.
    float lg[ROUTER_E];
    #pragma unroll
    for (int t = 0; t < TOK_T; ++t) {
        #pragma unroll
        for (int e = 0; e < ROUTER_E; ++e) {
            const float2 p = unpack2(acc[t][e]);
            float v = p.x + p.y;
            v += __shfl_xor_sync(0xffffffffu, v, 1);
            v += __shfl_xor_sync(0xffffffffu, v, 2);
            v += __shfl_xor_sync(0xffffffffu, v, 4);
            if (o == t) lg[e] = v;
        }
    }

    const int my_tok = base + o * 4 + g;               // token for epilogue lane
    if (o < TOK_T && my_tok < n_tokens) {
        const float4 n0 = __ldg(reinterpret_cast<const float4*>(noise + (size_t)my_tok * ROUTER_E));
        const float4 n1 = __ldg(reinterpret_cast<const float4*>(noise + (size_t)my_tok * ROUTER_E) + 1);

        lg[0] += __ldg(b + 0) + 0.1f * n0.x;
        lg[1] += __ldg(b + 1) + 0.1f * n0.y;
        lg[2] += __ldg(b + 2) + 0.1f * n0.z;
        lg[3] += __ldg(b + 3) + 0.1f * n0.w;
        lg[4] += __ldg(b + 4) + 0.1f * n1.x;
        lg[5] += __ldg(b + 5) + 0.1f * n1.y;
        lg[6] += __ldg(b + 6) + 0.1f * n1.z;
        lg[7] += __ldg(b + 7) + 0.1f * n1.w;

        // top-1 (strict > keeps lowest index on ties, matching jax.lax.top_k)
        int m1 = 0; float v1 = lg[0];
        #pragma unroll
        for (int e = 1; e < ROUTER_E; ++e)
            if (lg[e] > v1) { v1 = lg[e]; m1 = e; }
        // top-2
        int m2 = -1; float v2 = -CUDART_INF_F;
        #pragma unroll
        for (int e = 0; e < ROUTER_E; ++e)
            if (e != m1 && lg[e] > v2) { v2 = lg[e]; m2 = e; }

        // softmax over {v1, v2}, zeros elsewhere (exp(-inf)=0)
        const float ex  = __expf(v2 - v1);      // <= 1
        const float inv = 1.0f / (1.0f + ex);
        const float p1  = inv;
        const float p2  = ex * inv;

        float pv[ROUTER_E];
        #pragma unroll
        for (int e = 0; e < ROUTER_E; ++e)
            pv[e] = (e == m1) ? p1 : ((e == m2) ? p2 : 0.0f);

        float4* oo = reinterpret_cast<float4*>(out + (size_t)my_tok * ROUTER_E);
        oo[0] = make_float4(pv[0], pv[1], pv[2], pv[3]);
        oo[1] = make_float4(pv[4], pv[5], pv[6], pv[7]);

        // second output: top-k indices (stored as float32 after all probs)
        const long long probs = (long long)n_tokens * ROUTER_E;
        if (out_size >= probs + (long long)n_tokens * 2) {
            float2 iv = make_float2((float)m1, (float)m2);
            *reinterpret_cast<float2*>(out + probs + (size_t)my_tok * 2) = iv;
        }
    }
}

extern "C" void kernel_launch(void* const* d_in, const int* in_sizes, int n_in,
                              void* d_out, int out_size)
{
    const float* x     = (const float*)d_in[0];
    const float* W     = (const float*)d_in[1];
    const float* b     = (const float*)d_in[2];
    const float* noise = (const float*)d_in[3];
    float* out = (float*)d_out;

    const int n_tokens = in_sizes[0] / ROUTER_D;      // 32768
    const int tokens_per_block = 64;                  // 4 warps x 16 tokens
    const int blocks = (n_tokens + tokens_per_block - 1) / tokens_per_block;

    dynamic_router_kernel<<<blocks, 128>>>(x, W, b, noise, out,
                                           n_tokens, (long long)out_size);
}

// round 13
// speedup vs baseline: 1.6256x; 1.0227x over previous
#include <cuda_runtime.h>
#include <math_constants.h>

// DynamicRouter: logits = x @ W^T + b + 0.1*noise ; top-2 ; sparse softmax.
// x:[32768,768] f32, W:[8,768], b:[8], noise:[32768,8]
// out: [32768*8] probs, then [32768*2] top-k indices (as f32).
//
// Octet mapping (validated R7): 8 lanes x 16B = one full 128B line per LDG
// phase; T=4 tokens per octet group amortizes W -> 72 wf/token, L1=30%.
// R7 lesson: DRAM stuck at 43.6% = in-flight shortage (need ~244 loads/SM,
// had ~110 = 13.8 warps x 8). Fix: explicit 12-load x batch per iteration
// (unroll 3) -> ~166 in flight -> DRAM ~68%.

#define ROUTER_D 768
#define ROUTER_E 8
#define TOK_T    4
#define JSTEP    3

__device__ __forceinline__ void fma_x2(unsigned long long& d,
                                       unsigned long long a,
                                       unsigned long long b) {
    asm("fma.rn.f32x2 %0, %1, %2, %3;" : "=l"(d) : "l"(a), "l"(b), "l"(d));
}
__device__ __forceinline__ float2 unpack2(unsigned long long v) {
    float lo, hi;
    asm("mov.b64 {%0, %1}, %2;" : "=f"(lo), "=f"(hi) : "l"(v));
    return make_float2(lo, hi);
}

__global__ __launch_bounds__(128)
void dynamic_router_kernel(const float* __restrict__ x,
                           const float* __restrict__ W,
                           const float* __restrict__ b,
                           const float* __restrict__ noise,
                           float* __restrict__ out,
                           int n_tokens, long long out_size)
{
    const int tid  = threadIdx.x;
    const int warp = tid >> 5;
    const int lane = tid & 31;
    const int o    = lane & 7;   // 16B slot within a 128B (32-dim) step
    const int g    = lane >> 3;  // octet group 0..3

    // warp covers 16 tokens: token(t) = base + t*4 + g
    const int base = (blockIdx.x * 4 + warp) * (4 * TOK_T);

    // Row bases in 16B units (ulonglong2 = 4 floats)
    const ulonglong2* xr[TOK_T];
    #pragma unroll
    for (int t = 0; t < TOK_T; ++t) {
        int tk = base + t * 4 + g;
        tk = tk < n_tokens ? tk : 0;                   // clamp; stores guarded
        xr[t] = reinterpret_cast<const ulonglong2*>(x + (size_t)tk * ROUTER_D);
    }
    const ulonglong2* wr = reinterpret_cast<const ulonglong2*>(W);

    unsigned long long acc[TOK_T][ROUTER_E];
    #pragma unroll
    for (int t = 0; t < TOK_T; ++t)
        #pragma unroll
        for (int e = 0; e < ROUTER_E; ++e) acc[t][e] = 0ull;

    #pragma unroll 1
    for (int jj = 0; jj < ROUTER_D / 32; jj += JSTEP) {    // 8 iterations
        // Batch all 12 x loads first -> 12 DRAM loads in flight per warp.
        ulonglong2 xv[JSTEP][TOK_T];
        #pragma unroll
        for (int s = 0; s < JSTEP; ++s)
            #pragma unroll
            for (int t = 0; t < TOK_T; ++t)
                xv[s][t] = __ldg(&xr[t][(jj + s) * 8 + o]);

        // W loads are L1-resident; load just-in-time per expert.
        #pragma unroll
        for (int s = 0; s < JSTEP; ++s) {
            const int idx = (jj + s) * 8 + o;
            #pragma unroll
            for (int e = 0; e < ROUTER_E; ++e) {
                const ulonglong2 wv = __ldg(&wr[e * (ROUTER_D / 4) + idx]);
                #pragma unroll
                for (int t = 0; t < TOK_T; ++t) {
                    fma_x2(acc[t][e], xv[s][t].x, wv.x);
                    fma_x2(acc[t][e], xv[s][t].y, wv.y);
                }
            }
        }
    }

    // Reduce across the 8 lanes of the octet for each (t, e).
    // Lane with o == t keeps token t's logits.
    float lg[ROUTER_E];
    #pragma unroll
    for (int t = 0; t < TOK_T; ++t) {
        #pragma unroll
        for (int e = 0; e < ROUTER_E; ++e) {
            const float2 p = unpack2(acc[t][e]);
            float v = p.x + p.y;
            v += __shfl_xor_sync(0xffffffffu, v, 1);
            v += __shfl_xor_sync(0xffffffffu, v, 2);
            v += __shfl_xor_sync(0xffffffffu, v, 4);
            if (o == t) lg[e] = v;
        }
    }

    const int my_tok = base + o * 4 + g;               // token for epilogue lane
    if (o < TOK_T && my_tok < n_tokens) {
        const float4 n0 = __ldg(reinterpret_cast<const float4*>(noise + (size_t)my_tok * ROUTER_E));
        const float4 n1 = __ldg(reinterpret_cast<const float4*>(noise + (size_t)my_tok * ROUTER_E) + 1);

        lg[0] += __ldg(b + 0) + 0.1f * n0.x;
        lg[1] += __ldg(b + 1) + 0.1f * n0.y;
        lg[2] += __ldg(b + 2) + 0.1f * n0.z;
        lg[3] += __ldg(b + 3) + 0.1f * n0.w;
        lg[4] += __ldg(b + 4) + 0.1f * n1.x;
        lg[5] += __ldg(b + 5) + 0.1f * n1.y;
        lg[6] += __ldg(b + 6) + 0.1f * n1.z;
        lg[7] += __ldg(b + 7) + 0.1f * n1.w;

        // top-1 (strict > keeps lowest index on ties, matching jax.lax.top_k)
        int m1 = 0; float v1 = lg[0];
        #pragma unroll
        for (int e = 1; e < ROUTER_E; ++e)
            if (lg[e] > v1) { v1 = lg[e]; m1 = e; }
        // top-2
        int m2 = -1; float v2 = -CUDART_INF_F;
        #pragma unroll
        for (int e = 0; e < ROUTER_E; ++e)
            if (e != m1 && lg[e] > v2) { v2 = lg[e]; m2 = e; }

        // softmax over {v1, v2}, zeros elsewhere (exp(-inf)=0)
        const float ex  = __expf(v2 - v1);      // <= 1
        const float inv = 1.0f / (1.0f + ex);
        const float p1  = inv;
        const float p2  = ex * inv;

        float pv[ROUTER_E];
        #pragma unroll
        for (int e = 0; e < ROUTER_E; ++e)
            pv[e] = (e == m1) ? p1 : ((e == m2) ? p2 : 0.0f);

        float4* oo = reinterpret_cast<float4*>(out + (size_t)my_tok * ROUTER_E);
        oo[0] = make_float4(pv[0], pv[1], pv[2], pv[3]);
        oo[1] = make_float4(pv[4], pv[5], pv[6], pv[7]);

        // second output: top-k indices (stored as float32 after all probs)
        const long long probs = (long long)n_tokens * ROUTER_E;
        if (out_size >= probs + (long long)n_tokens * 2) {
            float2 iv = make_float2((float)m1, (float)m2);
            *reinterpret_cast<float2*>(out + probs + (size_t)my_tok * 2) = iv;
        }
    }
}

extern "C" void kernel_launch(void* const* d_in, const int* in_sizes, int n_in,
                              void* d_out, int out_size)
{
    const float* x     = (const float*)d_in[0];
    const float* W     = (const float*)d_in[1];
    const float* b     = (const float*)d_in[2];
    const float* noise = (const float*)d_in[3];
    float* out = (float*)d_out;

    const int n_tokens = in_sizes[0] / ROUTER_D;      // 32768
    const int tokens_per_block = 64;                  // 4 warps x 16 tokens
    const int blocks = (n_tokens + tokens_per_block - 1) / tokens_per_block;

    dynamic_router_kernel<<<blocks, 128>>>(x, W, b, noise, out,
                                           n_tokens, (long long)out_size);
}